// round 1
// baseline (speedup 1.0000x reference)
#include <cuda_runtime.h>
#include <math.h>

// Problem constants
#define Bb 2
#define Hh 48
#define Ww 48
#define Cc 192
#define NH 8
#define Nn 2304      // Hh*Ww
#define QW 8         // queries per warp
#define NWARPS 8
#define QT (QW*NWARPS)     // 64 queries per block
#define NTILES (Nn/QT)     // 36
#define SCALE 0.35355339059327373f  // 1/sqrt(8)

// smem: skA,skB,svA,svB: 4 * 2304 float4 = 147456 B
//       sbias: 2 tables * 8 warps * 48 pos * 8 q floats = 24576 B
#define SMEM_BYTES (Nn*4*16 + 2*NWARPS*48*8*4)

__global__ __launch_bounds__(256, 1)
void attn_aug2d_kernel(const float* __restrict__ inp,
                       const float* __restrict__ relw,
                       const float* __restrict__ relh,
                       float* __restrict__ out)
{
    extern __shared__ float smem[];
    float4* skA = (float4*)smem;      // [Nn] k dims 0..3
    float4* skB = skA + Nn;           // [Nn] k dims 4..7
    float4* svA = skB + Nn;           // [Nn] v dims 0..3
    float4* svB = svA + Nn;           // [Nn] v dims 4..7
    float*  sbias = (float*)(svB + Nn); // [2][NWARPS][48][8]

    const int tid  = threadIdx.x;
    const int warp = tid >> 5;
    const int lane = tid & 31;
    const int tile = blockIdx.x;
    const int h    = blockIdx.y;
    const int b    = blockIdx.z;

    // ---- stage K, V into smem (coalesced float4 loads) ----
    for (int m = tid; m < Nn; m += 256) {
        const float* base = inp + ((size_t)(b*Nn + m))*Cc + 64 + h*8; // k channels
        skA[m] = *(const float4*)(base);
        skB[m] = *(const float4*)(base + 4);
        svA[m] = *(const float4*)(base + 64);   // v = k + 64 channels
        svB[m] = *(const float4*)(base + 68);
    }

    // ---- per-warp separable bias tables ----
    // ph[qi][X] = q_i . rel_h[X - x_i + 47],  pw[qi][Y] = q_i . rel_w[Y - y_i + 47]
    const int q0 = tile*QT + warp*QW;
    for (int e = lane; e < 2*QW*48; e += 32) {
        int t   = e / (QW*48);          // 0 = ph (height), 1 = pw (width)
        int rem = e - t*(QW*48);
        int qi  = rem / 48;
        int pos = rem - qi*48;
        int n   = q0 + qi;
        int x   = n / 48;
        int y   = n - x*48;
        const float* qptr = inp + ((size_t)(b*Nn + n))*Cc + h*8;
        const float* rel  = (t == 0) ? (relh + (pos - x + 47)*8)
                                     : (relw + (pos - y + 47)*8);
        float s = 0.f;
        #pragma unroll
        for (int d = 0; d < 8; d++) s += qptr[d]*rel[d];
        sbias[((t*NWARPS + warp)*48 + pos)*8 + qi] = s * SCALE;
    }
    __syncthreads();

    // ---- load this warp's 8 queries into registers (pre-scaled) ----
    float4 qA[QW], qB[QW];
    #pragma unroll
    for (int i = 0; i < QW; i++) {
        const float* qptr = inp + ((size_t)(b*Nn + q0 + i))*Cc + h*8;
        float4 a = *(const float4*)(qptr);
        float4 c = *(const float4*)(qptr + 4);
        a.x *= SCALE; a.y *= SCALE; a.z *= SCALE; a.w *= SCALE;
        c.x *= SCALE; c.y *= SCALE; c.z *= SCALE; c.w *= SCALE;
        qA[i] = a; qB[i] = c;
    }

    float4 accA[QW], accB[QW];
    float  sum[QW];
    #pragma unroll
    for (int i = 0; i < QW; i++) {
        accA[i] = make_float4(0.f,0.f,0.f,0.f);
        accB[i] = make_float4(0.f,0.f,0.f,0.f);
        sum[i]  = 0.f;
    }

    const float* phbase = sbias + (0*NWARPS + warp)*48*8;
    const float* pwbase = sbias + (1*NWARPS + warp)*48*8;

    // ---- main loop: lanes stride over all 2304 keys ----
    int m = lane;
    int X = 0, Y = lane;               // lane < 32 < 48
    #pragma unroll 4
    for (int it = 0; it < Nn/32; it++) {
        float4 ka = skA[m], kb = skB[m];
        float4 va = svA[m], vb = svB[m];
        float4 pha = *(const float4*)(phbase + X*8);
        float4 phb = *(const float4*)(phbase + X*8 + 4);
        float4 pwa = *(const float4*)(pwbase + Y*8);
        float4 pwb = *(const float4*)(pwbase + Y*8 + 4);
        float phv[8] = {pha.x,pha.y,pha.z,pha.w,phb.x,phb.y,phb.z,phb.w};
        float pwv[8] = {pwa.x,pwa.y,pwa.z,pwa.w,pwb.x,pwb.y,pwb.z,pwb.w};

        #pragma unroll
        for (int i = 0; i < QW; i++) {
            float dot = qA[i].x*ka.x + qA[i].y*ka.y + qA[i].z*ka.z + qA[i].w*ka.w
                      + qB[i].x*kb.x + qB[i].y*kb.y + qB[i].z*kb.z + qB[i].w*kb.w;
            float w = __expf(dot + phv[i] + pwv[i]);
            sum[i] += w;
            accA[i].x += w*va.x; accA[i].y += w*va.y;
            accA[i].z += w*va.z; accA[i].w += w*va.w;
            accB[i].x += w*vb.x; accB[i].y += w*vb.y;
            accB[i].z += w*vb.z; accB[i].w += w*vb.w;
        }
        m += 32;
        Y += 32;
        if (Y >= 48) { Y -= 48; X += 1; }
    }

    // ---- warp reduction + writeback ----
    #pragma unroll
    for (int i = 0; i < QW; i++) {
        float  s = sum[i];
        float4 a = accA[i], c = accB[i];
        #pragma unroll
        for (int o = 16; o > 0; o >>= 1) {
            s   += __shfl_xor_sync(0xffffffffu, s,   o);
            a.x += __shfl_xor_sync(0xffffffffu, a.x, o);
            a.y += __shfl_xor_sync(0xffffffffu, a.y, o);
            a.z += __shfl_xor_sync(0xffffffffu, a.z, o);
            a.w += __shfl_xor_sync(0xffffffffu, a.w, o);
            c.x += __shfl_xor_sync(0xffffffffu, c.x, o);
            c.y += __shfl_xor_sync(0xffffffffu, c.y, o);
            c.z += __shfl_xor_sync(0xffffffffu, c.z, o);
            c.w += __shfl_xor_sync(0xffffffffu, c.w, o);
        }
        if (lane == 0) {
            float r = 1.0f / s;
            a.x *= r; a.y *= r; a.z *= r; a.w *= r;
            c.x *= r; c.y *= r; c.z *= r; c.w *= r;
            int n = q0 + i;
            float* op = out + ((size_t)(b*Nn + n))*64 + h*8;
            *(float4*)(op)     = a;
            *(float4*)(op + 4) = c;
        }
    }
}

extern "C" void kernel_launch(void* const* d_in, const int* in_sizes, int n_in,
                              void* d_out, int out_size)
{
    const float* inp  = (const float*)d_in[0];
    const float* relw = (const float*)d_in[1];
    const float* relh = (const float*)d_in[2];
    float* out = (float*)d_out;

    cudaFuncSetAttribute(attn_aug2d_kernel,
                         cudaFuncAttributeMaxDynamicSharedMemorySize, SMEM_BYTES);
    dim3 grid(NTILES, NH, Bb);
    attn_aug2d_kernel<<<grid, 256, SMEM_BYTES>>>(inp, relw, relh, out);
}

// round 2
// speedup vs baseline: 1.1581x; 1.1581x over previous
#include <cuda_runtime.h>
#include <math.h>

#define Bb 2
#define Hh 48
#define Ww 48
#define Cc 192
#define NH 8
#define Nn 2304            // Hh*Ww
#define QW 4               // queries per warp
#define NWARPS 16          // 512 threads
#define QT (QW*NWARPS)     // 64 queries per block
#define NTILES (Nn/QT)     // 36
// SCALE * log2(e): fold softmax scale and exp->ex2 conversion into q & bias
#define SL2E 0.5100420914154871f

// smem: skA,skB,svA,svB: 4 * 2304 * 16B = 147456
//       sph, spw: 2 * 16 warps * 48 pos * 4 q * 4B = 24576
#define SMEM_BYTES (Nn*4*16 + 2*NWARPS*48*QW*4)

typedef unsigned long long ull;

__device__ __forceinline__ ull pk2(float lo, float hi) {
    ull r; asm("mov.b64 %0,{%1,%2};" : "=l"(r) : "f"(lo), "f"(hi)); return r;
}
__device__ __forceinline__ void upk2(ull v, float& lo, float& hi) {
    asm("mov.b64 {%0,%1},%2;" : "=f"(lo), "=f"(hi) : "l"(v));
}
__device__ __forceinline__ ull fma2(ull a, ull b, ull c) {
    ull d; asm("fma.rn.f32x2 %0,%1,%2,%3;" : "=l"(d) : "l"(a), "l"(b), "l"(c)); return d;
}
__device__ __forceinline__ ull add2(ull a, ull b) {
    ull d; asm("add.rn.f32x2 %0,%1,%2;" : "=l"(d) : "l"(a), "l"(b)); return d;
}
__device__ __forceinline__ ull mul2(ull a, ull b) {
    ull d; asm("mul.rn.f32x2 %0,%1,%2;" : "=l"(d) : "l"(a), "l"(b)); return d;
}
__device__ __forceinline__ float ex2f(float x) {
    float r; asm("ex2.approx.f32 %0,%1;" : "=f"(r) : "f"(x)); return r;
}

__global__ __launch_bounds__(512, 1)
void attn_aug2d_kernel(const float* __restrict__ inp,
                       const float* __restrict__ relw,
                       const float* __restrict__ relh,
                       float* __restrict__ out)
{
    extern __shared__ float smem[];
    ulonglong2* skA = (ulonglong2*)smem;   // [Nn] k dims 0..3 as 2x f32x2
    ulonglong2* skB = skA + Nn;            // [Nn] k dims 4..7
    ulonglong2* svA = skB + Nn;            // [Nn] v dims 0..3
    ulonglong2* svB = svA + Nn;            // [Nn] v dims 4..7
    float* sph = (float*)(svB + Nn);              // [NWARPS][48][4]
    float* spw = sph + NWARPS*48*QW;              // [NWARPS][48][4]

    const int tid  = threadIdx.x;
    const int warp = tid >> 5;
    const int lane = tid & 31;
    const int tile = blockIdx.x;
    const int h    = blockIdx.y;
    const int b    = blockIdx.z;

    // ---- stage K, V into smem ----
    for (int m = tid; m < Nn; m += 512) {
        const float* base = inp + ((size_t)(b*Nn + m))*Cc + 64 + h*8; // k channels
        skA[m] = *(const ulonglong2*)(base);
        skB[m] = *(const ulonglong2*)(base + 4);
        svA[m] = *(const ulonglong2*)(base + 64);  // v = k + 64 channels
        svB[m] = *(const ulonglong2*)(base + 68);
    }

    // ---- per-warp separable bias tables (pre-scaled by SCALE*log2e) ----
    // sph[warp][X][qi] = (q_qi . rel_h[X - x + 47]) * SL2E
    // spw[warp][Y][qi] = (q_qi . rel_w[Y - y + 47]) * SL2E
    const int q0 = tile*QT + warp*QW;
    for (int e = lane; e < 2*48*QW; e += 32) {
        int t   = e / (48*QW);         // 0 = ph, 1 = pw
        int rem = e - t*(48*QW);
        int pos = rem >> 2;
        int qi  = rem & 3;
        int n   = q0 + qi;
        int x   = n / 48;
        int y   = n - x*48;
        const float* qptr = inp + ((size_t)(b*Nn + n))*Cc + h*8;
        const float* rel  = (t == 0) ? (relh + (pos - x + 47)*8)
                                     : (relw + (pos - y + 47)*8);
        float s = 0.f;
        #pragma unroll
        for (int d = 0; d < 8; d++) s += qptr[d]*rel[d];
        float* dst = (t == 0) ? sph : spw;
        dst[(warp*48 + pos)*QW + qi] = s * SL2E;
    }
    __syncthreads();

    // ---- pack queries cross-query: qp01[d]=(q0[d],q1[d]), qp23[d]=(q2[d],q3[d]) ----
    ull qp01[8], qp23[8];
    {
        const float* qa = inp + ((size_t)(b*Nn + q0 + 0))*Cc + h*8;
        const float* qb = inp + ((size_t)(b*Nn + q0 + 1))*Cc + h*8;
        const float* qc = inp + ((size_t)(b*Nn + q0 + 2))*Cc + h*8;
        const float* qd = inp + ((size_t)(b*Nn + q0 + 3))*Cc + h*8;
        #pragma unroll
        for (int d = 0; d < 8; d++) {
            qp01[d] = pk2(qa[d]*SL2E, qb[d]*SL2E);
            qp23[d] = pk2(qc[d]*SL2E, qd[d]*SL2E);
        }
    }

    ull acc0[4], acc1[4], acc2[4], acc3[4];
    #pragma unroll
    for (int p = 0; p < 4; p++) { acc0[p]=0; acc1[p]=0; acc2[p]=0; acc3[p]=0; }
    ull sum01 = 0, sum23 = 0;

    const ulonglong2* phb = (const ulonglong2*)(sph + warp*48*QW);
    const ulonglong2* pwb = (const ulonglong2*)(spw + warp*48*QW);

    // ---- main loop: lanes stride over all 2304 keys ----
    int m = lane;
    int X = 0, Y = lane;
    #pragma unroll 4
    for (int it = 0; it < Nn/32; it++) {
        ulonglong2 kA = skA[m], kB = skB[m];
        ulonglong2 vA = svA[m], vB = svB[m];
        ulonglong2 ph = phb[X];
        ulonglong2 pw = pwb[Y];

        // dots init with packed bias
        ull d01 = add2(ph.x, pw.x);
        ull d23 = add2(ph.y, pw.y);

        float k0,k1,k2,k3,k4,k5,k6,k7;
        upk2(kA.x,k0,k1); upk2(kA.y,k2,k3);
        upk2(kB.x,k4,k5); upk2(kB.y,k6,k7);
        ull kd;
        kd = pk2(k0,k0); d01 = fma2(qp01[0],kd,d01); d23 = fma2(qp23[0],kd,d23);
        kd = pk2(k1,k1); d01 = fma2(qp01[1],kd,d01); d23 = fma2(qp23[1],kd,d23);
        kd = pk2(k2,k2); d01 = fma2(qp01[2],kd,d01); d23 = fma2(qp23[2],kd,d23);
        kd = pk2(k3,k3); d01 = fma2(qp01[3],kd,d01); d23 = fma2(qp23[3],kd,d23);
        kd = pk2(k4,k4); d01 = fma2(qp01[4],kd,d01); d23 = fma2(qp23[4],kd,d23);
        kd = pk2(k5,k5); d01 = fma2(qp01[5],kd,d01); d23 = fma2(qp23[5],kd,d23);
        kd = pk2(k6,k6); d01 = fma2(qp01[6],kd,d01); d23 = fma2(qp23[6],kd,d23);
        kd = pk2(k7,k7); d01 = fma2(qp01[7],kd,d01); d23 = fma2(qp23[7],kd,d23);

        float e0,e1,e2,e3;
        upk2(d01,e0,e1); upk2(d23,e2,e3);
        float w0 = ex2f(e0), w1 = ex2f(e1), w2 = ex2f(e2), w3 = ex2f(e3);

        sum01 = add2(sum01, pk2(w0,w1));
        sum23 = add2(sum23, pk2(w2,w3));

        ull wd;
        wd = pk2(w0,w0);
        acc0[0]=fma2(wd,vA.x,acc0[0]); acc0[1]=fma2(wd,vA.y,acc0[1]);
        acc0[2]=fma2(wd,vB.x,acc0[2]); acc0[3]=fma2(wd,vB.y,acc0[3]);
        wd = pk2(w1,w1);
        acc1[0]=fma2(wd,vA.x,acc1[0]); acc1[1]=fma2(wd,vA.y,acc1[1]);
        acc1[2]=fma2(wd,vB.x,acc1[2]); acc1[3]=fma2(wd,vB.y,acc1[3]);
        wd = pk2(w2,w2);
        acc2[0]=fma2(wd,vA.x,acc2[0]); acc2[1]=fma2(wd,vA.y,acc2[1]);
        acc2[2]=fma2(wd,vB.x,acc2[2]); acc2[3]=fma2(wd,vB.y,acc2[3]);
        wd = pk2(w3,w3);
        acc3[0]=fma2(wd,vA.x,acc3[0]); acc3[1]=fma2(wd,vA.y,acc3[1]);
        acc3[2]=fma2(wd,vB.x,acc3[2]); acc3[3]=fma2(wd,vB.y,acc3[3]);

        m += 32;
        Y += 32;
        if (Y >= 48) { Y -= 48; X += 1; }
    }

    // ---- warp reduction (packed) ----
    #pragma unroll
    for (int o = 16; o > 0; o >>= 1) {
        sum01 = add2(sum01, __shfl_xor_sync(0xffffffffu, sum01, o));
        sum23 = add2(sum23, __shfl_xor_sync(0xffffffffu, sum23, o));
        #pragma unroll
        for (int p = 0; p < 4; p++) {
            acc0[p] = add2(acc0[p], __shfl_xor_sync(0xffffffffu, acc0[p], o));
            acc1[p] = add2(acc1[p], __shfl_xor_sync(0xffffffffu, acc1[p], o));
            acc2[p] = add2(acc2[p], __shfl_xor_sync(0xffffffffu, acc2[p], o));
            acc3[p] = add2(acc3[p], __shfl_xor_sync(0xffffffffu, acc3[p], o));
        }
    }

    if (lane == 0) {
        float s0,s1,s2,s3;
        upk2(sum01,s0,s1); upk2(sum23,s2,s3);
        float r0 = 1.0f/s0, r1 = 1.0f/s1, r2 = 1.0f/s2, r3 = 1.0f/s3;
        ull rd;
        ulonglong2 o01, o23;
        size_t obase = ((size_t)(b*Nn + q0))*64 + h*8;

        rd = pk2(r0,r0);
        o01.x = mul2(acc0[0],rd); o01.y = mul2(acc0[1],rd);
        o23.x = mul2(acc0[2],rd); o23.y = mul2(acc0[3],rd);
        *(ulonglong2*)(out + obase)      = o01;
        *(ulonglong2*)(out + obase + 4)  = o23;

        rd = pk2(r1,r1);
        o01.x = mul2(acc1[0],rd); o01.y = mul2(acc1[1],rd);
        o23.x = mul2(acc1[2],rd); o23.y = mul2(acc1[3],rd);
        *(ulonglong2*)(out + obase + 64)     = o01;
        *(ulonglong2*)(out + obase + 64 + 4) = o23;

        rd = pk2(r2,r2);
        o01.x = mul2(acc2[0],rd); o01.y = mul2(acc2[1],rd);
        o23.x = mul2(acc2[2],rd); o23.y = mul2(acc2[3],rd);
        *(ulonglong2*)(out + obase + 128)     = o01;
        *(ulonglong2*)(out + obase + 128 + 4) = o23;

        rd = pk2(r3,r3);
        o01.x = mul2(acc3[0],rd); o01.y = mul2(acc3[1],rd);
        o23.x = mul2(acc3[2],rd); o23.y = mul2(acc3[3],rd);
        *(ulonglong2*)(out + obase + 192)     = o01;
        *(ulonglong2*)(out + obase + 192 + 4) = o23;
    }
}

extern "C" void kernel_launch(void* const* d_in, const int* in_sizes, int n_in,
                              void* d_out, int out_size)
{
    const float* inp  = (const float*)d_in[0];
    const float* relw = (const float*)d_in[1];
    const float* relh = (const float*)d_in[2];
    float* out = (float*)d_out;

    cudaFuncSetAttribute(attn_aug2d_kernel,
                         cudaFuncAttributeMaxDynamicSharedMemorySize, SMEM_BYTES);
    dim3 grid(NTILES, NH, Bb);
    attn_aug2d_kernel<<<grid, 512, SMEM_BYTES>>>(inp, relw, relh, out);
}

// round 3
// speedup vs baseline: 1.1761x; 1.0155x over previous
#include <cuda_runtime.h>
#include <math.h>

#define Bb 2
#define Hh 48
#define Ww 48
#define Cc 192
#define NH 8
#define Nn 2304            // Hh*Ww
#define QW 4               // queries per warp
#define NWARPS 16          // 512 threads
#define QT (QW*NWARPS)     // 64 queries per block
#define NTILES (Nn/QT)     // 36
// SCALE * log2(e): fold softmax scale and exp->ex2 conversion into q & bias
#define SL2E 0.5100420914154871f

// smem: skA,skB,svA,svB: 4 * 2304 * 16B = 147456
//       sph, spw: 2 * 16 warps * 48 pos * 16B = 24576
#define SMEM_BYTES (Nn*4*16 + 2*NWARPS*48*16)

typedef unsigned long long ull;

__device__ __forceinline__ ull pk2(float lo, float hi) {
    ull r; asm("mov.b64 %0,{%1,%2};" : "=l"(r) : "f"(lo), "f"(hi)); return r;
}
__device__ __forceinline__ void upk2(ull v, float& lo, float& hi) {
    asm("mov.b64 {%0,%1},%2;" : "=f"(lo), "=f"(hi) : "l"(v));
}
__device__ __forceinline__ ull fma2(ull a, ull b, ull c) {
    ull d; asm("fma.rn.f32x2 %0,%1,%2,%3;" : "=l"(d) : "l"(a), "l"(b), "l"(c)); return d;
}
__device__ __forceinline__ ull add2(ull a, ull b) {
    ull d; asm("add.rn.f32x2 %0,%1,%2;" : "=l"(d) : "l"(a), "l"(b)); return d;
}
__device__ __forceinline__ ull mul2(ull a, ull b) {
    ull d; asm("mul.rn.f32x2 %0,%1,%2;" : "=l"(d) : "l"(a), "l"(b)); return d;
}
__device__ __forceinline__ float ex2f(float x) {
    float r; asm("ex2.approx.f32 %0,%1;" : "=f"(r) : "f"(x)); return r;
}

__global__ __launch_bounds__(512, 1)
void attn_aug2d_kernel(const float* __restrict__ inp,
                       const float* __restrict__ relw,
                       const float* __restrict__ relh,
                       float* __restrict__ out)
{
    extern __shared__ float smem[];
    ulonglong2* skA = (ulonglong2*)smem;   // [Nn] k dims 0..3
    ulonglong2* skB = skA + Nn;            // [Nn] k dims 4..7
    ulonglong2* svA = skB + Nn;            // [Nn] v dims 0..3
    ulonglong2* svB = svA + Nn;            // [Nn] v dims 4..7
    ulonglong2* sph = svB + Nn;            // [NWARPS][48] (4 floats = 16B each)
    ulonglong2* spw = sph + NWARPS*48;     // [NWARPS][48]

    const int tid  = threadIdx.x;
    const int warp = tid >> 5;
    const int lane = tid & 31;
    const int tile = blockIdx.x;
    const int h    = blockIdx.y;
    const int b    = blockIdx.z;

    // ---- stage K, V into smem ----
    for (int m = tid; m < Nn; m += 512) {
        const float* base = inp + ((size_t)(b*Nn + m))*Cc + 64 + h*8; // k channels
        skA[m] = *(const ulonglong2*)(base);
        skB[m] = *(const ulonglong2*)(base + 4);
        svA[m] = *(const ulonglong2*)(base + 64);  // v = k + 64 channels
        svB[m] = *(const ulonglong2*)(base + 68);
    }

    // ---- per-warp separable bias tables (pre-scaled by SCALE*log2e) ----
    // sph[warp][X] = 4 floats: (q_qi . rel_h[X - x_qi + 47]) * SL2E
    // spw[warp][Y] = 4 floats: (q_qi . rel_w[Y - y_qi + 47]) * SL2E
    const int q0 = tile*QT + warp*QW;
    for (int e = lane; e < 2*48*QW; e += 32) {
        int t   = e / (48*QW);         // 0 = ph, 1 = pw
        int rem = e - t*(48*QW);
        int pos = rem >> 2;
        int qi  = rem & 3;
        int n   = q0 + qi;
        int x   = n / 48;
        int y   = n - x*48;
        const float* qptr = inp + ((size_t)(b*Nn + n))*Cc + h*8;
        const float* rel  = (t == 0) ? (relh + (pos - x + 47)*8)
                                     : (relw + (pos - y + 47)*8);
        float s = 0.f;
        #pragma unroll
        for (int d = 0; d < 8; d++) s += qptr[d]*rel[d];
        float* dst = (float*)((t == 0) ? sph : spw);
        dst[(warp*48 + pos)*4 + qi] = s * SL2E;
    }
    __syncthreads();

    // ---- queries packed over dims: qXp[p] = (q_2p, q_2p+1) * SL2E ----
    ull q0p[4], q1p[4], q2p[4], q3p[4];
    {
        const ull sl2 = pk2(SL2E, SL2E);
        #pragma unroll
        for (int i = 0; i < QW; i++) {
            const float* qptr = inp + ((size_t)(b*Nn + q0 + i))*Cc + h*8;
            ulonglong2 a = *(const ulonglong2*)(qptr);
            ulonglong2 c = *(const ulonglong2*)(qptr + 4);
            ull* dst = (i==0)?q0p:(i==1)?q1p:(i==2)?q2p:q3p;
            dst[0] = mul2(a.x, sl2);
            dst[1] = mul2(a.y, sl2);
            dst[2] = mul2(c.x, sl2);
            dst[3] = mul2(c.y, sl2);
        }
    }

    // ---- pw register cache: Y = (lane + 32t) mod 48 has period 3 ----
    const ulonglong2* pww = spw + warp*48;
    ulonglong2 pwreg[3];
    #pragma unroll
    for (int j = 0; j < 3; j++) {
        int Yj = lane + 32*j;
        if (Yj >= 48) Yj -= 48;
        if (Yj >= 48) Yj -= 48;
        pwreg[j] = pww[Yj];
    }

    ull acc0[4], acc1[4], acc2[4], acc3[4];
    #pragma unroll
    for (int p = 0; p < 4; p++) { acc0[p]=0; acc1[p]=0; acc2[p]=0; acc3[p]=0; }
    float s0=0.f, s1=0.f, s2=0.f, s3=0.f;

    const ulonglong2* php = sph + warp*48;   // ph[X], X starts at 0 (lane < 48)
    int m = lane;
    int r = lane;                            // r = key - 48*X

    #pragma unroll 2
    for (int it = 0; it < Nn/(32*3); it++) {
        #pragma unroll
        for (int j = 0; j < 3; j++) {
            ulonglong2 kA = skA[m], kB = skB[m];
            ulonglong2 vA = svA[m], vB = svB[m];
            ulonglong2 ph = *php;

            ull pp01 = add2(ph.x, pwreg[j].x);
            ull pp23 = add2(ph.y, pwreg[j].y);

            ull d0 = mul2(q0p[0], kA.x);
            ull d1 = mul2(q1p[0], kA.x);
            ull d2 = mul2(q2p[0], kA.x);
            ull d3 = mul2(q3p[0], kA.x);
            d0 = fma2(q0p[1], kA.y, d0); d1 = fma2(q1p[1], kA.y, d1);
            d2 = fma2(q2p[1], kA.y, d2); d3 = fma2(q3p[1], kA.y, d3);
            d0 = fma2(q0p[2], kB.x, d0); d1 = fma2(q1p[2], kB.x, d1);
            d2 = fma2(q2p[2], kB.x, d2); d3 = fma2(q3p[2], kB.x, d3);
            d0 = fma2(q0p[3], kB.y, d0); d1 = fma2(q1p[3], kB.y, d1);
            d2 = fma2(q2p[3], kB.y, d2); d3 = fma2(q3p[3], kB.y, d3);

            float b0,b1,b2,b3, lo,hi;
            upk2(pp01, b0, b1); upk2(pp23, b2, b3);
            upk2(d0, lo, hi); float w0 = ex2f(lo + hi + b0);
            upk2(d1, lo, hi); float w1 = ex2f(lo + hi + b1);
            upk2(d2, lo, hi); float w2 = ex2f(lo + hi + b2);
            upk2(d3, lo, hi); float w3 = ex2f(lo + hi + b3);

            s0 += w0; s1 += w1; s2 += w2; s3 += w3;

            ull wd;
            wd = pk2(w0,w0);
            acc0[0]=fma2(wd,vA.x,acc0[0]); acc0[1]=fma2(wd,vA.y,acc0[1]);
            acc0[2]=fma2(wd,vB.x,acc0[2]); acc0[3]=fma2(wd,vB.y,acc0[3]);
            wd = pk2(w1,w1);
            acc1[0]=fma2(wd,vA.x,acc1[0]); acc1[1]=fma2(wd,vA.y,acc1[1]);
            acc1[2]=fma2(wd,vB.x,acc1[2]); acc1[3]=fma2(wd,vB.y,acc1[3]);
            wd = pk2(w2,w2);
            acc2[0]=fma2(wd,vA.x,acc2[0]); acc2[1]=fma2(wd,vA.y,acc2[1]);
            acc2[2]=fma2(wd,vB.x,acc2[2]); acc2[3]=fma2(wd,vB.y,acc2[3]);
            wd = pk2(w3,w3);
            acc3[0]=fma2(wd,vA.x,acc3[0]); acc3[1]=fma2(wd,vA.y,acc3[1]);
            acc3[2]=fma2(wd,vB.x,acc3[2]); acc3[3]=fma2(wd,vB.y,acc3[3]);

            m += 32;
            r += 32;
            if (r >= 48) { r -= 48; php++; }
        }
    }

    // ---- warp reduction (packed accs + scalar sums) ----
    #pragma unroll
    for (int o = 16; o > 0; o >>= 1) {
        s0 += __shfl_xor_sync(0xffffffffu, s0, o);
        s1 += __shfl_xor_sync(0xffffffffu, s1, o);
        s2 += __shfl_xor_sync(0xffffffffu, s2, o);
        s3 += __shfl_xor_sync(0xffffffffu, s3, o);
        #pragma unroll
        for (int p = 0; p < 4; p++) {
            acc0[p] = add2(acc0[p], __shfl_xor_sync(0xffffffffu, acc0[p], o));
            acc1[p] = add2(acc1[p], __shfl_xor_sync(0xffffffffu, acc1[p], o));
            acc2[p] = add2(acc2[p], __shfl_xor_sync(0xffffffffu, acc2[p], o));
            acc3[p] = add2(acc3[p], __shfl_xor_sync(0xffffffffu, acc3[p], o));
        }
    }

    if (lane == 0) {
        float r0 = 1.0f/s0, r1 = 1.0f/s1, r2 = 1.0f/s2, r3 = 1.0f/s3;
        ull rd;
        ulonglong2 oA, oB;
        size_t obase = ((size_t)(b*Nn + q0))*64 + h*8;

        rd = pk2(r0,r0);
        oA.x = mul2(acc0[0],rd); oA.y = mul2(acc0[1],rd);
        oB.x = mul2(acc0[2],rd); oB.y = mul2(acc0[3],rd);
        *(ulonglong2*)(out + obase)      = oA;
        *(ulonglong2*)(out + obase + 4)  = oB;

        rd = pk2(r1,r1);
        oA.x = mul2(acc1[0],rd); oA.y = mul2(acc1[1],rd);
        oB.x = mul2(acc1[2],rd); oB.y = mul2(acc1[3],rd);
        *(ulonglong2*)(out + obase + 64)     = oA;
        *(ulonglong2*)(out + obase + 64 + 4) = oB;

        rd = pk2(r2,r2);
        oA.x = mul2(acc2[0],rd); oA.y = mul2(acc2[1],rd);
        oB.x = mul2(acc2[2],rd); oB.y = mul2(acc2[3],rd);
        *(ulonglong2*)(out + obase + 128)     = oA;
        *(ulonglong2*)(out + obase + 128 + 4) = oB;

        rd = pk2(r3,r3);
        oA.x = mul2(acc3[0],rd); oA.y = mul2(acc3[1],rd);
        oB.x = mul2(acc3[2],rd); oB.y = mul2(acc3[3],rd);
        *(ulonglong2*)(out + obase + 192)     = oA;
        *(ulonglong2*)(out + obase + 192 + 4) = oB;
    }
}

extern "C" void kernel_launch(void* const* d_in, const int* in_sizes, int n_in,
                              void* d_out, int out_size)
{
    const float* inp  = (const float*)d_in[0];
    const float* relw = (const float*)d_in[1];
    const float* relh = (const float*)d_in[2];
    float* out = (float*)d_out;

    cudaFuncSetAttribute(attn_aug2d_kernel,
                         cudaFuncAttributeMaxDynamicSharedMemorySize, SMEM_BYTES);
    dim3 grid(NTILES, NH, Bb);
    attn_aug2d_kernel<<<grid, 512, SMEM_BYTES>>>(inp, relw, relh, out);
}